// round 1
// baseline (speedup 1.0000x reference)
#include <cuda_runtime.h>
#include <cstdint>
#include <cstddef>

#define NN   100000
#define EE   1600000
#define DDIM 128
#define RREL 8
#define BBAS 4
#define OUTD 64

// ---------------- scratch (no cudaMalloc allowed) ----------------
__device__ float g_agg[(size_t)NN * RREL * DDIM];   // 409.6 MB
__device__ float g_cnt[NN * RREL];                  // 3.2 MB
__device__ float g_gs[(size_t)NN * DDIM];           // 51.2 MB
__device__ float g_gc[NN];                          // 0.4 MB
__device__ float g_Z[(size_t)NN * 640];             // 256 MB

// ---------------- f32x2 packed math helpers ----------------
__device__ __forceinline__ unsigned long long pk2(float x, float y) {
    unsigned long long r;
    asm("mov.b64 %0, {%1,%2};" : "=l"(r) : "f"(x), "f"(y));
    return r;
}
__device__ __forceinline__ void upk2(unsigned long long v, float& x, float& y) {
    asm("mov.b64 {%0,%1}, %2;" : "=f"(x), "=f"(y) : "l"(v));
}
__device__ __forceinline__ unsigned long long ffma2(unsigned long long a,
                                                    unsigned long long b,
                                                    unsigned long long c) {
    unsigned long long d;
    asm("fma.rn.f32x2 %0, %1, %2, %3;" : "=l"(d) : "l"(a), "l"(b), "l"(c));
    return d;
}

// ---------------- edge scatter: agg (by dst,rel) + gate (by src) ----------------
__global__ void edge_kernel(const float* __restrict__ h,
                            const int* __restrict__ src,
                            const int* __restrict__ dst,
                            const int* __restrict__ et) {
    int e = blockIdx.x * 8 + (threadIdx.x >> 5);
    if (e >= EE) return;
    int lane = threadIdx.x & 31;
    int s = src[e], t = dst[e], q = et[e];

    float4 a = ((const float4*)(h + (size_t)s * DDIM))[lane];
    float4 b = ((const float4*)(h + (size_t)t * DDIM))[lane];

    float* ap = g_agg + ((size_t)t * RREL + q) * DDIM + lane * 4;
    atomicAdd(ap + 0, a.x);
    atomicAdd(ap + 1, a.y);
    atomicAdd(ap + 2, a.z);
    atomicAdd(ap + 3, a.w);

    float dx = a.x - b.x, dy = a.y - b.y, dz = a.z - b.z, dw = a.w - b.w;
    float* gp = g_gs + (size_t)s * DDIM + lane * 4;
    atomicAdd(gp + 0, dx * dx);
    atomicAdd(gp + 1, dy * dy);
    atomicAdd(gp + 2, dz * dz);
    atomicAdd(gp + 3, dw * dw);

    if (lane == 0) {
        atomicAdd(&g_cnt[t * RREL + q], 1.0f);
        atomicAdd(&g_gc[s], 1.0f);
    }
}

// ---------------- Z build: z[n,b,d] = sum_r comp[r,b]*agg[n,r,d]/max(cnt,1); Z[:,512:640]=h ----------------
__global__ void z_kernel(const float* __restrict__ h,
                         const float* __restrict__ comp,   // [R,B]
                         float* __restrict__ Z) {
    int n = blockIdx.x;
    int d = threadIdx.x;     // 0..127
    __shared__ float icnt[RREL];
    __shared__ float sc[RREL * BBAS];
    if (d < RREL * BBAS) sc[d] = comp[d];
    if (d < RREL) {
        float c = g_cnt[n * RREL + d];
        icnt[d] = 1.0f / fmaxf(c, 1.0f);
    }
    __syncthreads();

    const float* ag = g_agg + (size_t)n * (RREL * DDIM);
    float acc[BBAS] = {0.f, 0.f, 0.f, 0.f};
#pragma unroll
    for (int r = 0; r < RREL; ++r) {
        float v = ag[r * DDIM + d] * icnt[r];
#pragma unroll
        for (int b = 0; b < BBAS; ++b) acc[b] += sc[r * BBAS + b] * v;
    }
    float* zr = Z + (size_t)n * 640;
#pragma unroll
    for (int b = 0; b < BBAS; ++b) zr[b * DDIM + d] = acc[b];
    zr[512 + d] = h[(size_t)n * DDIM + d];
}

// ---------------- tiled fp32x2 GEMM, fused epilogues ----------------
// C[M,NC] = epi( A[M,K] @ [B1 (K1 rows); B2 (K-K1 rows)] )
// EPI 0: relu(acc + bias)                -> out
// EPI 1: hn=relu(acc+bias); tau=tanh(gs/max(gc,1)); out = hp + tau*(hn-hp)
// EPI 2: acc + bias                      -> out
template <int NC, int EPI>
__global__ __launch_bounds__(128)
void gemm_k(const float* __restrict__ A, int M, int K,
            const float* __restrict__ B1, int K1,
            const float* __restrict__ B2,
            const float* __restrict__ bias,
            const float* __restrict__ hprev,
            const float* __restrict__ gs,
            const float* __restrict__ gc,
            float* __restrict__ out) {
    extern __shared__ float sm[];
    float* As = sm;                      // [64 k][68] transposed (k-major)
    float* Bs = sm + 64 * 68;            // [64 k][NC+4]

    const int tid = threadIdx.x;
    const int tx = tid & 15;             // 16 col groups
    const int ty = tid >> 4;             // 8 row groups (8 rows each)
    const int row0 = blockIdx.x * 64;

    constexpr int NCT = NC / 16;         // cols per thread (8 or 4)
    constexpr int NPR = NCT / 2;         // f32x2 pairs (4 or 2)

    unsigned long long acc[8][NPR];
#pragma unroll
    for (int i = 0; i < 8; ++i)
#pragma unroll
        for (int j = 0; j < NPR; ++j) acc[i][j] = 0ull;

    const int nch = K >> 6;
    for (int c = 0; c < nch; ++c) {
        const int k0 = c << 6;
        // stage A (transpose to k-major)
#pragma unroll
        for (int u = 0; u < 8; ++u) {
            int fid = u * 128 + tid;          // 0..1023 float4 slots
            int r = fid >> 4;                 // tile row 0..63
            int kq = fid & 15;                // float4 within 64-k chunk
            int grow = row0 + r;
            float4 v = make_float4(0.f, 0.f, 0.f, 0.f);
            if (grow < M) v = *(const float4*)(A + (size_t)grow * K + k0 + kq * 4);
            As[(kq * 4 + 0) * 68 + r] = v.x;
            As[(kq * 4 + 1) * 68 + r] = v.y;
            As[(kq * 4 + 2) * 68 + r] = v.z;
            As[(kq * 4 + 3) * 68 + r] = v.w;
        }
        // stage B
        const float* Bp = (k0 < K1) ? (B1 + (size_t)k0 * NC)
                                    : (B2 + (size_t)(k0 - K1) * NC);
#pragma unroll
        for (int u = 0; u < (64 * NC / 4) / 128; ++u) {
            int fid = u * 128 + tid;
            int r = fid / (NC / 4);
            int c4 = fid % (NC / 4);
            float4 v = *(const float4*)(Bp + (size_t)r * NC + c4 * 4);
            *(float4*)(&Bs[r * (NC + 4) + c4 * 4]) = v;
        }
        __syncthreads();

#pragma unroll
        for (int k = 0; k < 64; ++k) {
            float4 a0 = *(const float4*)(As + k * 68 + ty * 8);
            float4 a1 = *(const float4*)(As + k * 68 + ty * 8 + 4);
            unsigned long long bp[NPR];
            const float* brow = Bs + k * (NC + 4) + tx * NCT;
#pragma unroll
            for (int j = 0; j < NPR; ++j)
                bp[j] = *(const unsigned long long*)(brow + 2 * j);
            float av[8] = {a0.x, a0.y, a0.z, a0.w, a1.x, a1.y, a1.z, a1.w};
#pragma unroll
            for (int i = 0; i < 8; ++i) {
                unsigned long long a2 = pk2(av[i], av[i]);
#pragma unroll
                for (int j = 0; j < NPR; ++j) acc[i][j] = ffma2(a2, bp[j], acc[i][j]);
            }
        }
        __syncthreads();
    }

    // epilogue
#pragma unroll
    for (int i = 0; i < 8; ++i) {
        int row = row0 + ty * 8 + i;
        if (row >= M) break;
        float cv[NCT];
#pragma unroll
        for (int j = 0; j < NPR; ++j) upk2(acc[i][j], cv[2 * j], cv[2 * j + 1]);
        const int fbase = tx * NCT;
        if (EPI == 0) {
#pragma unroll
            for (int j = 0; j < NCT; ++j) cv[j] = fmaxf(cv[j] + bias[fbase + j], 0.f);
        } else if (EPI == 1) {
            float ig = 1.0f / fmaxf(gc[row], 1.0f);
#pragma unroll
            for (int j = 0; j < NCT; ++j) {
                int f = fbase + j;
                float hn = fmaxf(cv[j] + bias[f], 0.f);
                float hp = hprev[(size_t)row * DDIM + f];
                float tau = tanhf(gs[(size_t)row * DDIM + f] * ig);
                cv[j] = hp + tau * (hn - hp);
            }
        } else {
#pragma unroll
            for (int j = 0; j < NCT; ++j) cv[j] += bias[fbase + j];
        }
#pragma unroll
        for (int j4 = 0; j4 < NCT; j4 += 4) {
            *(float4*)(out + (size_t)row * NC + fbase + j4) =
                make_float4(cv[j4], cv[j4 + 1], cv[j4 + 2], cv[j4 + 3]);
        }
    }
}

// ---------------- launch ----------------
extern "C" void kernel_launch(void* const* d_in, const int* in_sizes, int n_in,
                              void* d_out, int out_size) {
    (void)in_sizes; (void)n_in; (void)out_size;
    const float* x      = (const float*)d_in[0];
    const int*   src    = (const int*)d_in[1];
    const int*   dst    = (const int*)d_in[2];
    const int*   et     = (const int*)d_in[3];
    const float* projW  = (const float*)d_in[4];
    const float* projb  = (const float*)d_in[5];
    const float* basis1 = (const float*)d_in[6];
    const float* comp1  = (const float*)d_in[7];
    const float* root1  = (const float*)d_in[8];
    const float* bias1  = (const float*)d_in[9];
    const float* basis2 = (const float*)d_in[10];
    const float* comp2  = (const float*)d_in[11];
    const float* root2  = (const float*)d_in[12];
    const float* bias2  = (const float*)d_in[13];
    const float* outW   = (const float*)d_in[14];
    const float* outb   = (const float*)d_in[15];

    float* o  = (float*)d_out;
    float* L0 = o + (size_t)NN * OUTD;        // latents[0]
    float* L1 = L0 + (size_t)NN * DDIM;       // latents[1]
    float* L2 = L1 + (size_t)NN * DDIM;       // latents[2]

    float *agg, *cnt, *gsv, *gcv, *Z;
    cudaGetSymbolAddress((void**)&agg, g_agg);
    cudaGetSymbolAddress((void**)&cnt, g_cnt);
    cudaGetSymbolAddress((void**)&gsv, g_gs);
    cudaGetSymbolAddress((void**)&gcv, g_gc);
    cudaGetSymbolAddress((void**)&Z,   g_Z);

    const int SMEM128 = (64 * 68 + 64 * 132) * 4;   // 51200
    const int SMEM64  = (64 * 68 + 64 * 68) * 4;    // 34816
    cudaFuncSetAttribute(gemm_k<128, 0>, cudaFuncAttributeMaxDynamicSharedMemorySize, SMEM128);
    cudaFuncSetAttribute(gemm_k<128, 1>, cudaFuncAttributeMaxDynamicSharedMemorySize, SMEM128);
    cudaFuncSetAttribute(gemm_k<64, 2>,  cudaFuncAttributeMaxDynamicSharedMemorySize, SMEM64);

    const int gblocks = (NN + 63) / 64;   // 1563

    // input projection: h0 = relu(x @ projW + projb)
    gemm_k<128, 0><<<gblocks, 128, SMEM128>>>(x, NN, 128, projW, 128, nullptr,
                                              projb, nullptr, nullptr, nullptr, L0);

    const float* hs[3]     = {L0, L1, L2};
    const float* basisA[2] = {basis1, basis2};
    const float* compA[2]  = {comp1, comp2};
    const float* rootA[2]  = {root1, root2};
    const float* biasA[2]  = {bias1, bias2};

    for (int l = 0; l < 2; ++l) {
        cudaMemsetAsync(agg, 0, (size_t)NN * RREL * DDIM * sizeof(float));
        cudaMemsetAsync(cnt, 0, (size_t)NN * RREL * sizeof(float));
        cudaMemsetAsync(gsv, 0, (size_t)NN * DDIM * sizeof(float));
        cudaMemsetAsync(gcv, 0, (size_t)NN * sizeof(float));

        edge_kernel<<<EE / 8, 256>>>(hs[l], src, dst, et);
        z_kernel<<<NN, 128>>>(hs[l], compA[l], Z);
        gemm_k<128, 1><<<gblocks, 128, SMEM128>>>(Z, NN, 640, basisA[l], 512, rootA[l],
                                                  biasA[l], hs[l], gsv, gcv,
                                                  (float*)hs[l + 1]);
    }

    // final: out = h2 @ outW + outb
    gemm_k<64, 2><<<gblocks, 128, SMEM64>>>(L2, NN, 128, outW, 128, nullptr,
                                            outb, nullptr, nullptr, nullptr, o);
}

// round 2
// speedup vs baseline: 1.1301x; 1.1301x over previous
#include <cuda_runtime.h>
#include <cstdint>
#include <cstddef>

#define NN   100000
#define EE   1600000
#define DDIM 128
#define RREL 8
#define BBAS 4
#define OUTD 64

// ---------------- scratch (no cudaMalloc allowed) ----------------
__device__ float g_agg[(size_t)NN * RREL * DDIM];   // 409.6 MB
__device__ float g_cnt[NN * RREL];                  // 3.2 MB
__device__ float g_gs[(size_t)NN * DDIM];           // 51.2 MB
__device__ float g_gc[NN];                          // 0.4 MB
__device__ float g_Z[(size_t)NN * 640];             // 256 MB

// ---------------- f32x2 packed math helpers ----------------
__device__ __forceinline__ unsigned long long pk2(float x, float y) {
    unsigned long long r;
    asm("mov.b64 %0, {%1,%2};" : "=l"(r) : "f"(x), "f"(y));
    return r;
}
__device__ __forceinline__ void upk2(unsigned long long v, float& x, float& y) {
    asm("mov.b64 {%0,%1}, %2;" : "=f"(x), "=f"(y) : "l"(v));
}
__device__ __forceinline__ unsigned long long ffma2(unsigned long long a,
                                                    unsigned long long b,
                                                    unsigned long long c) {
    unsigned long long d;
    asm("fma.rn.f32x2 %0, %1, %2, %3;" : "=l"(d) : "l"(a), "l"(b), "l"(c));
    return d;
}

// ---------------- vector RED + cp.async helpers ----------------
__device__ __forceinline__ void red4(float* p, float x, float y, float z, float w) {
    asm volatile("red.global.add.v4.f32 [%0], {%1,%2,%3,%4};"
                 :: "l"(p), "f"(x), "f"(y), "f"(z), "f"(w) : "memory");
}
__device__ __forceinline__ void cp16(uint32_t dst, const void* src, int srcsz) {
    asm volatile("cp.async.ca.shared.global [%0], [%1], 16, %2;"
                 :: "r"(dst), "l"(src), "r"(srcsz));
}
__device__ __forceinline__ void cp_commit() {
    asm volatile("cp.async.commit_group;");
}
template <int N>
__device__ __forceinline__ void cp_wait() {
    asm volatile("cp.async.wait_group %0;" :: "n"(N));
}

// ---------------- edge scatter: agg (by dst,rel) + gate (by src) ----------------
__global__ void edge_kernel(const float* __restrict__ h,
                            const int* __restrict__ src,
                            const int* __restrict__ dst,
                            const int* __restrict__ et) {
    int e = blockIdx.x * 8 + (threadIdx.x >> 5);
    if (e >= EE) return;
    int lane = threadIdx.x & 31;
    int s = src[e], t = dst[e], q = et[e];

    float4 a = ((const float4*)(h + (size_t)s * DDIM))[lane];
    float4 b = ((const float4*)(h + (size_t)t * DDIM))[lane];

    float* ap = g_agg + ((size_t)t * RREL + q) * DDIM + lane * 4;
    red4(ap, a.x, a.y, a.z, a.w);

    float dx = a.x - b.x, dy = a.y - b.y, dz = a.z - b.z, dw = a.w - b.w;
    float* gp = g_gs + (size_t)s * DDIM + lane * 4;
    red4(gp, dx * dx, dy * dy, dz * dz, dw * dw);

    if (lane == 0) {
        atomicAdd(&g_cnt[t * RREL + q], 1.0f);
        atomicAdd(&g_gc[s], 1.0f);
    }
}

// ---------------- Z build ----------------
__global__ void z_kernel(const float* __restrict__ h,
                         const float* __restrict__ comp,   // [R,B]
                         float* __restrict__ Z) {
    int n = blockIdx.x;
    int d = threadIdx.x;     // 0..127
    __shared__ float icnt[RREL];
    __shared__ float sc[RREL * BBAS];
    if (d < RREL * BBAS) sc[d] = comp[d];
    if (d < RREL) {
        float c = g_cnt[n * RREL + d];
        icnt[d] = 1.0f / fmaxf(c, 1.0f);
    }
    __syncthreads();

    const float* ag = g_agg + (size_t)n * (RREL * DDIM);
    float acc[BBAS] = {0.f, 0.f, 0.f, 0.f};
#pragma unroll
    for (int r = 0; r < RREL; ++r) {
        float v = ag[r * DDIM + d] * icnt[r];
#pragma unroll
        for (int b = 0; b < BBAS; ++b) acc[b] += sc[r * BBAS + b] * v;
    }
    float* zr = Z + (size_t)n * 640;
#pragma unroll
    for (int b = 0; b < BBAS; ++b) zr[b * DDIM + d] = acc[b];
    zr[512 + d] = h[(size_t)n * DDIM + d];
}

// ---------------- cp.async double-buffered fp32x2 GEMM ----------------
// C[M,NC] = epi( A[M,K] @ [B1 (K1 rows); B2 (K-K1 rows)] )
// EPI 0: relu(acc + bias)
// EPI 1: hn=relu(acc+bias); tau=tanh(gs/max(gc,1)); out = hp + tau*(hn-hp)
// EPI 2: acc + bias
template <int NC, int EPI>
__global__ __launch_bounds__(128)
void gemm_k(const float* __restrict__ A, int M, int K,
            const float* __restrict__ B1, int K1,
            const float* __restrict__ B2,
            const float* __restrict__ bias,
            const float* __restrict__ hprev,
            const float* __restrict__ gs,
            const float* __restrict__ gc,
            float* __restrict__ out) {
    constexpr int APAD = 68;              // A row stride (floats)
    constexpr int BPAD = NC + 4;          // B row stride (floats)
    extern __shared__ float sm[];
    float* As[2] = {sm, sm + 64 * APAD};                       // [buf][64 r][APAD] row-major
    float* Bs[2] = {sm + 2 * 64 * APAD,
                    sm + 2 * 64 * APAD + 64 * BPAD};           // [buf][64 k][BPAD]

    const int tid = threadIdx.x;
    const int tx = tid & 15;             // 16 col groups
    const int ty = tid >> 4;             // 8 row groups (8 rows each)
    const int row0 = blockIdx.x * 64;

    constexpr int NCT = NC / 16;         // cols per thread (8 or 4)
    constexpr int NPR = NCT / 2;         // f32x2 pairs

    unsigned long long acc[8][NPR];
#pragma unroll
    for (int i = 0; i < 8; ++i)
#pragma unroll
        for (int j = 0; j < NPR; ++j) acc[i][j] = 0ull;

    const int nch = K >> 6;

    auto load_chunk = [&](int c, int buf) {
        const int k0 = c << 6;
        // A tile: 64 rows x 16 float4 = 1024 slots, 8 per thread
#pragma unroll
        for (int u = 0; u < 8; ++u) {
            int fid = u * 128 + tid;
            int r = fid >> 4;
            int q = fid & 15;
            int grow = row0 + r;
            uint32_t dsts = (uint32_t)__cvta_generic_to_shared(As[buf] + r * APAD + q * 4);
            const float* srcp = A + (size_t)(grow < M ? grow : 0) * K + k0 + q * 4;
            cp16(dsts, srcp, grow < M ? 16 : 0);
        }
        // B tile: 64 rows x NC/4 float4
        const float* Bp = (k0 < K1) ? (B1 + (size_t)k0 * NC)
                                    : (B2 + (size_t)(k0 - K1) * NC);
#pragma unroll
        for (int u = 0; u < (64 * NC / 4) / 128; ++u) {
            int fid = u * 128 + tid;
            int r = fid / (NC / 4);
            int c4 = fid % (NC / 4);
            uint32_t dsts = (uint32_t)__cvta_generic_to_shared(Bs[buf] + r * BPAD + c4 * 4);
            cp16(dsts, Bp + (size_t)r * NC + c4 * 4, 16);
        }
    };

    load_chunk(0, 0);
    cp_commit();

    for (int c = 0; c < nch; ++c) {
        const int buf = c & 1;
        if (c + 1 < nch) {
            load_chunk(c + 1, buf ^ 1);
            cp_commit();
            cp_wait<1>();
        } else {
            cp_wait<0>();
        }
        __syncthreads();

        const float* Ab = As[buf];
        const float* Bb = Bs[buf];
#pragma unroll
        for (int kk0 = 0; kk0 < 64; kk0 += 4) {
            float4 av[8];
#pragma unroll
            for (int i = 0; i < 8; ++i)
                av[i] = *(const float4*)(Ab + (ty * 8 + i) * APAD + kk0);
#pragma unroll
            for (int kk = 0; kk < 4; ++kk) {
                unsigned long long bp[NPR];
                const float* brow = Bb + (kk0 + kk) * BPAD + tx * NCT;
#pragma unroll
                for (int j = 0; j < NPR; ++j)
                    bp[j] = *(const unsigned long long*)(brow + 2 * j);
#pragma unroll
                for (int i = 0; i < 8; ++i) {
                    float a = (kk == 0) ? av[i].x : (kk == 1) ? av[i].y
                             : (kk == 2) ? av[i].z : av[i].w;
                    unsigned long long a2 = pk2(a, a);
#pragma unroll
                    for (int j = 0; j < NPR; ++j) acc[i][j] = ffma2(a2, bp[j], acc[i][j]);
                }
            }
        }
        __syncthreads();
    }

    // epilogue
#pragma unroll
    for (int i = 0; i < 8; ++i) {
        int row = row0 + ty * 8 + i;
        if (row >= M) break;
        float cv[NCT];
#pragma unroll
        for (int j = 0; j < NPR; ++j) upk2(acc[i][j], cv[2 * j], cv[2 * j + 1]);
        const int fbase = tx * NCT;
        if (EPI == 0) {
#pragma unroll
            for (int j = 0; j < NCT; ++j) cv[j] = fmaxf(cv[j] + bias[fbase + j], 0.f);
        } else if (EPI == 1) {
            float ig = 1.0f / fmaxf(gc[row], 1.0f);
#pragma unroll
            for (int j = 0; j < NCT; ++j) {
                int f = fbase + j;
                float hn = fmaxf(cv[j] + bias[f], 0.f);
                float hp = hprev[(size_t)row * DDIM + f];
                float tau = tanhf(gs[(size_t)row * DDIM + f] * ig);
                cv[j] = hp + tau * (hn - hp);
            }
        } else {
#pragma unroll
            for (int j = 0; j < NCT; ++j) cv[j] += bias[fbase + j];
        }
#pragma unroll
        for (int j4 = 0; j4 < NCT; j4 += 4) {
            *(float4*)(out + (size_t)row * NC + fbase + j4) =
                make_float4(cv[j4], cv[j4 + 1], cv[j4 + 2], cv[j4 + 3]);
        }
    }
}

// ---------------- launch ----------------
extern "C" void kernel_launch(void* const* d_in, const int* in_sizes, int n_in,
                              void* d_out, int out_size) {
    (void)in_sizes; (void)n_in; (void)out_size;
    const float* x      = (const float*)d_in[0];
    const int*   src    = (const int*)d_in[1];
    const int*   dst    = (const int*)d_in[2];
    const int*   et     = (const int*)d_in[3];
    const float* projW  = (const float*)d_in[4];
    const float* projb  = (const float*)d_in[5];
    const float* basis1 = (const float*)d_in[6];
    const float* comp1  = (const float*)d_in[7];
    const float* root1  = (const float*)d_in[8];
    const float* bias1  = (const float*)d_in[9];
    const float* basis2 = (const float*)d_in[10];
    const float* comp2  = (const float*)d_in[11];
    const float* root2  = (const float*)d_in[12];
    const float* bias2  = (const float*)d_in[13];
    const float* outW   = (const float*)d_in[14];
    const float* outb   = (const float*)d_in[15];

    float* o  = (float*)d_out;
    float* L0 = o + (size_t)NN * OUTD;        // latents[0]
    float* L1 = L0 + (size_t)NN * DDIM;       // latents[1]
    float* L2 = L1 + (size_t)NN * DDIM;       // latents[2]

    float *agg, *cnt, *gsv, *gcv, *Z;
    cudaGetSymbolAddress((void**)&agg, g_agg);
    cudaGetSymbolAddress((void**)&cnt, g_cnt);
    cudaGetSymbolAddress((void**)&gsv, g_gs);
    cudaGetSymbolAddress((void**)&gcv, g_gc);
    cudaGetSymbolAddress((void**)&Z,   g_Z);

    const int SMEM128 = (2 * 64 * 68 + 2 * 64 * 132) * 4;   // 102400
    const int SMEM64  = (2 * 64 * 68 + 2 * 64 * 68) * 4;    // 69632
    cudaFuncSetAttribute(gemm_k<128, 0>, cudaFuncAttributeMaxDynamicSharedMemorySize, SMEM128);
    cudaFuncSetAttribute(gemm_k<128, 1>, cudaFuncAttributeMaxDynamicSharedMemorySize, SMEM128);
    cudaFuncSetAttribute(gemm_k<64, 2>,  cudaFuncAttributeMaxDynamicSharedMemorySize, SMEM64);

    const int gblocks = (NN + 63) / 64;   // 1563

    // input projection: h0 = relu(x @ projW + projb)
    gemm_k<128, 0><<<gblocks, 128, SMEM128>>>(x, NN, 128, projW, 128, nullptr,
                                              projb, nullptr, nullptr, nullptr, L0);

    const float* hs[3]     = {L0, L1, L2};
    const float* basisA[2] = {basis1, basis2};
    const float* compA[2]  = {comp1, comp2};
    const float* rootA[2]  = {root1, root2};
    const float* biasA[2]  = {bias1, bias2};

    for (int l = 0; l < 2; ++l) {
        cudaMemsetAsync(agg, 0, (size_t)NN * RREL * DDIM * sizeof(float));
        cudaMemsetAsync(cnt, 0, (size_t)NN * RREL * sizeof(float));
        cudaMemsetAsync(gsv, 0, (size_t)NN * DDIM * sizeof(float));
        cudaMemsetAsync(gcv, 0, (size_t)NN * sizeof(float));

        edge_kernel<<<EE / 8, 256>>>(hs[l], src, dst, et);
        z_kernel<<<NN, 128>>>(hs[l], compA[l], Z);
        gemm_k<128, 1><<<gblocks, 128, SMEM128>>>(Z, NN, 640, basisA[l], 512, rootA[l],
                                                  biasA[l], hs[l], gsv, gcv,
                                                  (float*)hs[l + 1]);
    }

    // final: out = h2 @ outW + outb
    gemm_k<64, 2><<<gblocks, 128, SMEM64>>>(L2, NN, 128, outW, 128, nullptr,
                                            outb, nullptr, nullptr, nullptr, o);
}